// round 4
// baseline (speedup 1.0000x reference)
#include <cuda_runtime.h>

#define N_ROWS 16384
#define D      2048
#define NUM_LABELS 1024
#define NUM_CAMS   8
#define S (NUM_LABELS * NUM_CAMS)   // 8192 segments
#define MAXC 32                     // max rows per segment cached in smem

// ---- scratch (device globals; no allocation allowed) ----
__device__ int    g_count[S];
__device__ int    g_offset[S];
__device__ int    g_order[N_ROWS];
__device__ int    g_done;
__device__ double g_partial[S];

// ---------------------------------------------------------------------------
// K_PREP: ONE block, 1024 threads. Does everything the old 4 kernels did:
//   - detect int64 vs int32 storage of labels/cam_ids (odd-word probe)
//   - smem histogram of 16384 segment ids into 8192 bins
//   - in-smem exclusive scan (8 entries/thread + Hillis-Steele over totals)
//   - scatter: smem cursor starts at offset, atomicAdd return IS the position
//   - reset g_done for k_main's last-block protocol
// ---------------------------------------------------------------------------
__global__ __launch_bounds__(1024) void k_prep(const int* __restrict__ lab32,
                                               const int* __restrict__ cam32) {
    __shared__ int cnt_s[S];      // histogram -> exclusive offsets -> cursors
    __shared__ int tsum[1024];
    __shared__ int s_any;
    int t = threadIdx.x;

    // zero histogram (each thread owns contiguous [t*8, t*8+8))
#pragma unroll
    for (int j = 0; j < 8; j++) cnt_s[t * 8 + j] = 0;
    if (t == 0) { s_any = 0; g_done = 0; }
    __syncthreads();

    // int64 detection: if arrays are little-endian int64 with values < 2^31,
    // all odd int32 words of cam_ids are zero; if int32, cam values 0..7 make
    // odd positions nonzero with overwhelming probability.
    int probe = 0;
    for (int i = t; i < N_ROWS / 8; i += 1024) probe |= cam32[2 * i + 1];
    if (probe) atomicOr(&s_any, 1);
    __syncthreads();
    int stride = s_any ? 1 : 2;

    // segment ids (16/thread, coalesced) + smem histogram
    int seg[16];
#pragma unroll
    for (int j = 0; j < 16; j++) {
        int i = t + j * 1024;
        int lab = lab32[i * stride];
        int cam = cam32[i * stride];
        seg[j] = lab * NUM_CAMS + cam;
        atomicAdd(&cnt_s[seg[j]], 1);
    }
    __syncthreads();

    // exclusive scan: local 8-entry serial prefix + Hillis-Steele over totals
    int c[8];
    int run = 0;
#pragma unroll
    for (int j = 0; j < 8; j++) { c[j] = cnt_s[t * 8 + j]; run += c[j]; }
    tsum[t] = run;
    __syncthreads();
    for (int off = 1; off < 1024; off <<= 1) {
        int v = (t >= off) ? tsum[t - off] : 0;
        __syncthreads();
        tsum[t] += v;
        __syncthreads();
    }
    int ex = (t == 0) ? 0 : tsum[t - 1];
#pragma unroll
    for (int j = 0; j < 8; j++) {
        int s = t * 8 + j;
        g_count[s]  = c[j];
        g_offset[s] = ex;
        cnt_s[s]    = ex;   // cursor initialized to exclusive offset
        ex += c[j];
    }
    __syncthreads();

    // scatter: atomicAdd on the offset-initialized cursor returns the slot
#pragma unroll
    for (int j = 0; j < 16; j++) {
        int i = t + j * 1024;
        int pos = atomicAdd(&cnt_s[seg[j]], 1);
        g_order[pos] = i;
    }
}

__device__ __forceinline__ float sl1(float d) {
    float ad = fabsf(d);
    return ad < 1.0f ? 0.5f * d * d : ad - 0.5f;
}

// ---------------------------------------------------------------------------
// K_MAIN: one CTA per segment. Pass 1 sums rows -> mean; pass 2 SmoothL1 vs
// mean (pass-2 row reads hit L1: same CTA just read them). cnt<=1 segments
// contribute exactly zero (mean == the row). The LAST block to finish runs
// the deterministic final reduction over g_partial and writes the scalar.
// ---------------------------------------------------------------------------
__global__ __launch_bounds__(256) void k_main(const float* __restrict__ feats,
                                              float* __restrict__ out) {
    __shared__ int   rows_s[MAXC];
    __shared__ float wsum[8];
    __shared__ bool  s_last;
    int s = blockIdx.x;
    int t = threadIdx.x;
    int cnt = g_count[s];

    if (cnt >= 2) {
        int base = g_offset[s];
        int ccap = min(cnt, MAXC);
        if (t < ccap) rows_s[t] = g_order[base + t];
        __syncthreads();

        // thread t owns cols [4t,4t+4) and [1024+4t,1024+4t+4)
        float4 s0 = make_float4(0.f, 0.f, 0.f, 0.f);
        float4 s1 = make_float4(0.f, 0.f, 0.f, 0.f);
        for (int r = 0; r < cnt; r++) {
            int row = (r < MAXC) ? rows_s[r] : g_order[base + r];
            const float4* p = (const float4*)(feats + (size_t)row * D);
            float4 a = p[t];
            float4 b = p[t + 256];
            s0.x += a.x; s0.y += a.y; s0.z += a.z; s0.w += a.w;
            s1.x += b.x; s1.y += b.y; s1.z += b.z; s1.w += b.w;
        }
        float inv = 1.0f / (float)cnt;
        float4 m0 = make_float4(s0.x * inv, s0.y * inv, s0.z * inv, s0.w * inv);
        float4 m1 = make_float4(s1.x * inv, s1.y * inv, s1.z * inv, s1.w * inv);

        float acc = 0.f;
        for (int r = 0; r < cnt; r++) {
            int row = (r < MAXC) ? rows_s[r] : g_order[base + r];
            const float4* p = (const float4*)(feats + (size_t)row * D);
            float4 a = p[t];          // L1 hit
            float4 b = p[t + 256];
            acc += sl1(a.x - m0.x) + sl1(a.y - m0.y) + sl1(a.z - m0.z) + sl1(a.w - m0.w);
            acc += sl1(b.x - m1.x) + sl1(b.y - m1.y) + sl1(b.z - m1.z) + sl1(b.w - m1.w);
        }
#pragma unroll
        for (int off = 16; off; off >>= 1)
            acc += __shfl_down_sync(0xffffffffu, acc, off);
        if ((t & 31) == 0) wsum[t >> 5] = acc;
        __syncthreads();
        if (t == 0) {
            float tot = 0.f;
#pragma unroll
            for (int w = 0; w < 8; w++) tot += wsum[w];
            g_partial[s] = (double)tot;
        }
    } else {
        if (t == 0) g_partial[s] = 0.0;
    }

    // last-block-does-final-reduction protocol (deterministic reduction tree)
    if (t == 0) {
        __threadfence();
        int d = atomicAdd(&g_done, 1);
        s_last = (d == S - 1);
    }
    __syncthreads();
    if (!s_last) return;
    __threadfence();

    __shared__ double red[256];
    double local = 0.0;
    for (int i = t; i < S; i += 256) local += g_partial[i];
    red[t] = local;
    __syncthreads();
    for (int off = 128; off; off >>= 1) {
        if (t < off) red[t] += red[t + off];
        __syncthreads();
    }
    if (t == 0) out[0] = (float)(red[0] / ((double)N_ROWS * (double)D));
}

extern "C" void kernel_launch(void* const* d_in, const int* in_sizes, int n_in,
                              void* d_out, int out_size) {
    const float* feats = (const float*)d_in[0];
    const int*   lab32 = (const int*)d_in[1];
    const int*   cam32 = (const int*)d_in[2];
    float* out = (float*)d_out;

    k_prep<<<1, 1024>>>(lab32, cam32);
    k_main<<<S, 256>>>(feats, out);
}